// round 10
// baseline (speedup 1.0000x reference)
#include <cuda_runtime.h>

#define NN 8192
#define DD 128
#define MARGIN 0.3f
#define TOPK 512          // top_k(flat2,1024) == top-512 of original, each twice
#define SELCAP 4096
#define CANDCAP 65536     // K (entries in [tau, tau*]) evidence-calibrated ~12-15k; 4x+ headroom

// -------- device scratch (no allocations allowed) --------
__device__ float        d_a[NN];        // a_i = sq2_i - 2*c_ii + margin
__device__ float        d_sq2[NN];
__device__ unsigned int d_M[NN];        // per-row max loss, as uint bits (losses >= 0)
__device__ double       d_sum;          // sum of off-diagonal relu losses
__device__ float        d_tau;
__device__ float        d_gmax;
__device__ int          d_nsel;
__device__ int          d_selRows[SELCAP];
__device__ int          d_ncand;
__device__ float        d_cand[CANDCAP];

// -------- reductions (blockDim == 1024 for block variants) --------
__device__ __forceinline__ float warpRedSumF(float v){
  #pragma unroll
  for (int o=16;o;o>>=1) v += __shfl_xor_sync(0xffffffffu, v, o);
  return v;
}
__device__ __forceinline__ int warpRedSumI(int v){
  #pragma unroll
  for (int o=16;o;o>>=1) v += __shfl_xor_sync(0xffffffffu, v, o);
  return v;
}
__device__ __forceinline__ float warpRedMaxF(float v){
  #pragma unroll
  for (int o=16;o;o>>=1) v = fmaxf(v, __shfl_xor_sync(0xffffffffu, v, o));
  return v;
}
__device__ __forceinline__ int blockRedSumI(int v, int* sh){
  v = warpRedSumI(v);
  int w = threadIdx.x >> 5, l = threadIdx.x & 31;
  if (l == 0) sh[w] = v;
  __syncthreads();
  if (w == 0){ int x = sh[l]; x = warpRedSumI(x); if (l == 0) sh[0] = x; }
  __syncthreads();
  int r = sh[0];
  __syncthreads();
  return r;
}
__device__ __forceinline__ float blockRedSumF(float v, float* sh){
  v = warpRedSumF(v);
  int w = threadIdx.x >> 5, l = threadIdx.x & 31;
  if (l == 0) sh[w] = v;
  __syncthreads();
  if (w == 0){ float x = sh[l]; x = warpRedSumF(x); if (l == 0) sh[0] = x; }
  __syncthreads();
  float r = sh[0];
  __syncthreads();
  return r;
}
__device__ __forceinline__ float blockRedMaxF(float v, float* sh){
  v = warpRedMaxF(v);
  int w = threadIdx.x >> 5, l = threadIdx.x & 31;
  if (l == 0) sh[w] = v;
  __syncthreads();
  if (w == 0){ float x = sh[l]; x = warpRedMaxF(x); if (l == 0) sh[0] = x; }
  __syncthreads();
  float r = sh[0];
  __syncthreads();
  return r;
}

// -------- k0: reset scratch (graph replays must be deterministic) --------
__global__ void k_init(){
  int i = blockIdx.x * blockDim.x + threadIdx.x;
  if (i < NN) d_M[i] = 0u;
  if (i == 0){ d_sum = 0.0; d_ncand = 0; d_nsel = 0; }
}

// -------- k1: per-row sq2 and a_i (exact fp32, avoids bias on diagonal term) --------
__global__ void k_prep(const float* __restrict__ p1, const float* __restrict__ p2){
  int warp = (blockIdx.x * blockDim.x + threadIdx.x) >> 5;
  int lane = threadIdx.x & 31;
  if (warp >= NN) return;
  const float4* p1r = (const float4*)(p1 + warp * DD);
  const float4* p2r = (const float4*)(p2 + warp * DD);
  float4 x = p1r[lane];
  float4 y = p2r[lane];
  float sq = y.x*y.x + y.y*y.y + y.z*y.z + y.w*y.w;
  float ci = x.x*y.x + x.y*y.y + x.z*y.z + x.w*y.w;
  sq = warpRedSumF(sq);
  ci = warpRedSumF(ci);
  if (lane == 0){
    d_sq2[warp] = sq;
    d_a[warp]   = sq - 2.0f * ci + MARGIN;
  }
}

// -------- k2: fused GEMM + epilogue (sum + per-row max) --------
#define BT 128
#define KC 32

__global__ __launch_bounds__(256, 2) void k_main(const float* __restrict__ p1,
                                                 const float* __restrict__ p2){
  __shared__ __align__(16) float As[KC][BT + 4];   // [k][row], stride 132 (16B-aligned rows)
  __shared__ __align__(16) float Bs[KC][BT + 4];   // [k][col]
  int tid = threadIdx.x;
  int tx = tid & 15, ty = tid >> 4;
  int rowBase = blockIdx.y * BT, colBase = blockIdx.x * BT;

  float acc[8][8];
  #pragma unroll
  for (int i=0;i<8;i++)
    #pragma unroll
    for (int j=0;j<8;j++) acc[i][j] = 0.0f;

  for (int kc = 0; kc < DD; kc += KC){
    #pragma unroll
    for (int p=0;p<4;p++){
      int q  = tid + p * 256;        // 0..1023 : 128 rows x 8 float4
      int r  = q >> 3;
      int c4 = q & 7;
      float4 v = *(const float4*)(p1 + (rowBase + r) * DD + kc + c4 * 4);
      As[c4*4+0][r] = v.x; As[c4*4+1][r] = v.y; As[c4*4+2][r] = v.z; As[c4*4+3][r] = v.w;
      float4 w = *(const float4*)(p2 + (colBase + r) * DD + kc + c4 * 4);
      Bs[c4*4+0][r] = w.x; Bs[c4*4+1][r] = w.y; Bs[c4*4+2][r] = w.z; Bs[c4*4+3][r] = w.w;
    }
    __syncthreads();
    #pragma unroll 8
    for (int k=0;k<KC;k++){
      float a[8], b[8];
      *(float4*)&a[0] = *(const float4*)&As[k][ty * 4];
      *(float4*)&a[4] = *(const float4*)&As[k][64 + ty * 4];
      *(float4*)&b[0] = *(const float4*)&Bs[k][tx * 4];
      *(float4*)&b[4] = *(const float4*)&Bs[k][64 + tx * 4];
      #pragma unroll
      for (int i=0;i<8;i++)
        #pragma unroll
        for (int j=0;j<8;j++) acc[i][j] = fmaf(a[i], b[j], acc[i][j]);
    }
    __syncthreads();
  }

  // epilogue: loss = relu(a_i - sq2_j + 2*c_ij), skip diagonal
  int gr[8], gc[8];
  float av[8], s2[8];
  #pragma unroll
  for (int i=0;i<8;i++){
    int lr = (i < 4) ? (ty*4 + i) : (64 + ty*4 + i - 4);
    gr[i] = rowBase + lr;
    av[i] = d_a[gr[i]];
  }
  #pragma unroll
  for (int j=0;j<8;j++){
    int lc = (j < 4) ? (tx*4 + j) : (64 + tx*4 + j - 4);
    gc[j] = colBase + lc;
    s2[j] = d_sq2[gc[j]];
  }
  float lsum = 0.0f;
  float rmax[8];
  #pragma unroll
  for (int i=0;i<8;i++){
    float rm = 0.0f;
    #pragma unroll
    for (int j=0;j<8;j++){
      float loss = fmaxf(fmaf(2.0f, acc[i][j], av[i] - s2[j]), 0.0f);
      if (gr[i] != gc[j]){ lsum += loss; rm = fmaxf(rm, loss); }
    }
    rmax[i] = rm;
  }

  __shared__ unsigned int smax[BT];
  __shared__ float sred[8];
  if (tid < BT) smax[tid] = 0u;
  __syncthreads();
  #pragma unroll
  for (int i=0;i<8;i++){
    int lr = (i < 4) ? (ty*4 + i) : (64 + ty*4 + i - 4);
    atomicMax(&smax[lr], __float_as_uint(rmax[i]));   // valid: values >= 0
  }
  lsum = warpRedSumF(lsum);
  if ((tid & 31) == 0) sred[tid >> 5] = lsum;
  __syncthreads();
  if (tid < BT) atomicMax(&d_M[rowBase + tid], smax[tid]);
  if (tid == 0){
    float bs = 0.0f;
    #pragma unroll
    for (int w=0;w<8;w++) bs += sred[w];
    atomicAdd(&d_sum, (double)bs);
  }
}

// -------- k3: find 512th-largest row max -> tau, select rows --------
__global__ __launch_bounds__(1024) void k_select(){
  __shared__ float sM[NN];
  __shared__ int   shi[32];
  __shared__ float shf[32];
  __shared__ int   cnt_s;
  int tid = threadIdx.x;
  float lm = 0.0f;
  for (int i = tid; i < NN; i += 1024){
    float v = __uint_as_float(d_M[i]);
    sM[i] = v;
    lm = fmaxf(lm, v);
  }
  __syncthreads();
  float gmax = blockRedMaxF(lm, shf);

  // binary search largest t with count(M >= t) >= TOPK  (== 512th largest row max)
  float lo = 0.0f, hi = gmax * 1.0001f + 1e-6f;
  for (int it=0; it<48; it++){
    float mid = 0.5f * (lo + hi);
    int c = 0;
    for (int i = tid; i < NN; i += 1024) c += (sM[i] >= mid) ? 1 : 0;
    c = blockRedSumI(c, shi);
    if (c >= TOPK) lo = mid; else hi = mid;
  }
  // slack for fp recompute noise in pass 2; tau <= v512rowmax <= tau* guaranteed
  float tau = lo * 0.9999f - 0.01f;

  if (tid == 0) cnt_s = 0;
  __syncthreads();
  for (int i = tid; i < NN; i += 1024){
    if (sM[i] >= tau){
      int p = atomicAdd(&cnt_s, 1);
      if (p < SELCAP) d_selRows[p] = i;
    }
  }
  __syncthreads();
  if (tid == 0){
    d_nsel = (cnt_s < SELCAP) ? cnt_s : SELCAP;
    d_tau  = tau;
    d_gmax = gmax;
  }
}

// -------- k4: recompute selected rows, collect candidates >= tau --------
__global__ __launch_bounds__(256) void k_collect(const float* __restrict__ p1,
                                                 const float* __restrict__ p2){
  int nsel = d_nsel;
  int rt = blockIdx.y;
  if (rt * 64 >= nsel) return;
  int nrows = min(64, nsel - rt * 64);

  __shared__ __align__(16) float As[64][DD];
  __shared__ float aS[64];
  __shared__ int   ri[64];
  int tid = threadIdx.x;
  if (tid < 64){
    if (tid < nrows){
      int r = d_selRows[rt * 64 + tid];
      ri[tid] = r;
      aS[tid] = d_a[r];
    } else { ri[tid] = -1; aS[tid] = 0.0f; }
  }
  __syncthreads();
  #pragma unroll
  for (int p=0;p<8;p++){
    int q  = tid + p * 256;      // 64 rows x 32 float4
    int r  = q >> 5;
    int c4 = q & 31;
    float4 v = make_float4(0.f,0.f,0.f,0.f);
    if (r < nrows) v = *(const float4*)(p1 + ri[r] * DD + c4 * 4);
    *(float4*)&As[r][c4 * 4] = v;
  }
  __syncthreads();

  int col = blockIdx.x * 256 + tid;
  float acc[64];
  #pragma unroll
  for (int r=0;r<64;r++) acc[r] = 0.0f;
  const float4* p2r = (const float4*)(p2 + col * DD);
  for (int k4 = 0; k4 < 32; k4++){
    float4 b = p2r[k4];
    #pragma unroll
    for (int r=0;r<64;r++){
      float4 a = *(const float4*)&As[r][k4 * 4];     // broadcast across warp
      acc[r] = fmaf(a.x, b.x, acc[r]);
      acc[r] = fmaf(a.y, b.y, acc[r]);
      acc[r] = fmaf(a.z, b.z, acc[r]);
      acc[r] = fmaf(a.w, b.w, acc[r]);
    }
  }
  float s2c = d_sq2[col];
  float tau = d_tau;
  #pragma unroll
  for (int r=0;r<64;r++){
    if (r < nrows){
      float loss = fmaxf(fmaf(2.0f, acc[r], aS[r] - s2c), 0.0f);
      if (loss >= tau && ri[r] != col){
        int p = atomicAdd(&d_ncand, 1);
        if (p < CANDCAP) d_cand[p] = loss;
      }
    }
  }
}

// -------- k5: exact top-512 stats from candidates (global-memory scan, L2-hot) --------
__global__ __launch_bounds__(1024) void k_final(float* __restrict__ out){
  __shared__ float shf[32];
  __shared__ int   shi[32];
  int tid = threadIdx.x;
  int nc = d_ncand;
  if (nc > CANDCAP) nc = CANDCAP;
  float gmax = d_gmax;

  // positives among candidates
  int pc = 0; float ps = 0.0f;
  for (int i = tid; i < nc; i += 1024){
    float v = d_cand[i];
    if (v > 0.0f){ pc++; ps += v; }
  }
  int pcnt   = blockRedSumI(pc, shi);
  float psum = blockRedSumF(ps, shf);

  float avg;
  if (pcnt >= TOPK){
    // top-512 all positive: threshold-search exact 512th value with tie handling
    float lo = 0.0f, hi = gmax * 1.0001f + 1e-6f;
    for (int it=0; it<48; it++){
      float mid = 0.5f * (lo + hi);
      int c = 0;
      for (int i = tid; i < nc; i += 1024) c += (d_cand[i] >= mid) ? 1 : 0;
      c = blockRedSumI(c, shi);
      if (c >= TOPK) lo = mid; else hi = mid;
    }
    int ch = 0; float sh = 0.0f;
    for (int i = tid; i < nc; i += 1024){
      float v = d_cand[i];
      if (v >= hi){ ch++; sh += v; }
    }
    int   chi = blockRedSumI(ch, shi);
    float shs = blockRedSumF(sh, shf);
    avg = (shs + (float)(TOPK - chi) * lo) / (float)TOPK;
  } else if (pcnt > 0){
    avg = psum / (float)pcnt;    // all positives are inside the top-512
  } else {
    avg = gmax;                  // reference fallback: topv[0] == global max
  }

  if (tid == 0){
    out[0] = avg;                                              // avg_loss
    out[1] = (float)(d_sum / ((double)NN * (double)(NN - 1))); // all_loss
  }
}

extern "C" void kernel_launch(void* const* d_in, const int* in_sizes, int n_in,
                              void* d_out, int out_size){
  (void)in_sizes; (void)n_in; (void)out_size;
  const float* p1 = (const float*)d_in[0];
  const float* p2 = (const float*)d_in[1];
  float* out = (float*)d_out;

  k_init   <<<(NN + 255) / 256, 256>>>();
  k_prep   <<<NN / 8, 256>>>(p1, p2);
  k_main   <<<dim3(64, 64), 256>>>(p1, p2);
  k_select <<<1, 1024>>>();
  k_collect<<<dim3(32, 64), 256>>>(p1, p2);
  k_final  <<<1, 1024>>>(out);
}

// round 14
// speedup vs baseline: 1.6723x; 1.6723x over previous
#include <cuda_runtime.h>
#include <cuda_bf16.h>
#include <cstdint>

#define NN 8192
#define DD 128
#define MARGIN 0.3f
#define TOPK 512
#define SELCAP 4096
#define CANDCAP 65536

// ---------------- device scratch ----------------
__device__ float        d_a[NN];
__device__ float        d_sq2[NN];
__device__ unsigned int d_M[NN];
__device__ double       d_sum;
__device__ float        d_tau;
__device__ float        d_gmax;
__device__ int          d_nsel;
__device__ int          d_selRows[SELCAP];
__device__ int          d_ncand;
__device__ float        d_cand[CANDCAP];
// bf16 hi/lo split copies of inputs
__device__ __nv_bfloat16 d_p1h[NN*DD];
__device__ __nv_bfloat16 d_p1l[NN*DD];
__device__ __nv_bfloat16 d_p2h[NN*DD];
__device__ __nv_bfloat16 d_p2l[NN*DD];

// ---------------- SIMT tensor helpers (sm_80+ ISA, valid on compute_103) ----
__device__ __forceinline__ uint32_t smem_u32(const void* p){
  uint32_t a;
  asm("{ .reg .u64 t; cvta.to.shared.u64 t, %1; cvt.u32.u64 %0, t; }" : "=r"(a) : "l"(p));
  return a;
}
__device__ __forceinline__ void ldmx4(uint32_t* r, uint32_t addr){
  asm volatile("ldmatrix.sync.aligned.m8n8.x4.shared.b16 {%0,%1,%2,%3}, [%4];"
    : "=r"(r[0]), "=r"(r[1]), "=r"(r[2]), "=r"(r[3]) : "r"(addr));
}
__device__ __forceinline__ void mma_bf16(float* d, const uint32_t* a, const uint32_t* b){
  asm volatile(
    "mma.sync.aligned.m16n8k16.row.col.f32.bf16.bf16.f32 "
    "{%0,%1,%2,%3}, {%4,%5,%6,%7}, {%8,%9}, {%0,%1,%2,%3};"
    : "+f"(d[0]), "+f"(d[1]), "+f"(d[2]), "+f"(d[3])
    : "r"(a[0]), "r"(a[1]), "r"(a[2]), "r"(a[3]), "r"(b[0]), "r"(b[1]));
}

// ---------------- reductions ----------------
__device__ __forceinline__ float warpRedSumF(float v){
  #pragma unroll
  for (int o=16;o;o>>=1) v += __shfl_xor_sync(0xffffffffu, v, o);
  return v;
}
__device__ __forceinline__ int warpRedSumI(int v){
  #pragma unroll
  for (int o=16;o;o>>=1) v += __shfl_xor_sync(0xffffffffu, v, o);
  return v;
}
__device__ __forceinline__ float warpRedMaxF(float v){
  #pragma unroll
  for (int o=16;o;o>>=1) v = fmaxf(v, __shfl_xor_sync(0xffffffffu, v, o));
  return v;
}
__device__ __forceinline__ int blockRedSumI(int v, int* sh){
  v = warpRedSumI(v);
  int w = threadIdx.x >> 5, l = threadIdx.x & 31;
  if (l == 0) sh[w] = v;
  __syncthreads();
  if (w == 0){ int x = sh[l]; x = warpRedSumI(x); if (l == 0) sh[0] = x; }
  __syncthreads();
  int r = sh[0];
  __syncthreads();
  return r;
}
__device__ __forceinline__ float blockRedSumF(float v, float* sh){
  v = warpRedSumF(v);
  int w = threadIdx.x >> 5, l = threadIdx.x & 31;
  if (l == 0) sh[w] = v;
  __syncthreads();
  if (w == 0){ float x = sh[l]; x = warpRedSumF(x); if (l == 0) sh[0] = x; }
  __syncthreads();
  float r = sh[0];
  __syncthreads();
  return r;
}
__device__ __forceinline__ float blockRedMaxF(float v, float* sh){
  v = warpRedMaxF(v);
  int w = threadIdx.x >> 5, l = threadIdx.x & 31;
  if (l == 0) sh[w] = v;
  __syncthreads();
  if (w == 0){ float x = sh[l]; x = warpRedMaxF(x); if (l == 0) sh[0] = x; }
  __syncthreads();
  float r = sh[0];
  __syncthreads();
  return r;
}

// -------- k0: reset scratch --------
__global__ void k_init(){
  int i = blockIdx.x * blockDim.x + threadIdx.x;
  if (i < NN) d_M[i] = 0u;
  if (i == 0){ d_sum = 0.0; d_ncand = 0; d_nsel = 0; }
}

// -------- k_conv: fp32 -> bf16 hi/lo split --------
__global__ void k_conv(const float* __restrict__ p1, const float* __restrict__ p2){
  int base = blockIdx.x * blockDim.x + threadIdx.x;
  int stride = gridDim.x * blockDim.x;
  for (int i = base; i < NN*DD; i += stride){
    float x = p1[i];
    __nv_bfloat16 h = __float2bfloat16(x);
    d_p1h[i] = h;
    d_p1l[i] = __float2bfloat16(x - __bfloat162float(h));
    float y = p2[i];
    __nv_bfloat16 g = __float2bfloat16(y);
    d_p2h[i] = g;
    d_p2l[i] = __float2bfloat16(y - __bfloat162float(g));
  }
}

// -------- k_prep: exact fp32 sq2 / a --------
__global__ void k_prep(const float* __restrict__ p1, const float* __restrict__ p2){
  int warp = (blockIdx.x * blockDim.x + threadIdx.x) >> 5;
  int lane = threadIdx.x & 31;
  if (warp >= NN) return;
  const float4* p1r = (const float4*)(p1 + warp * DD);
  const float4* p2r = (const float4*)(p2 + warp * DD);
  float4 x = p1r[lane];
  float4 y = p2r[lane];
  float sq = y.x*y.x + y.y*y.y + y.z*y.z + y.w*y.w;
  float ci = x.x*y.x + x.y*y.y + x.z*y.z + x.w*y.w;
  sq = warpRedSumF(sq);
  ci = warpRedSumF(ci);
  if (lane == 0){
    d_sq2[warp] = sq;
    d_a[warp]   = sq - 2.0f * ci + MARGIN;
  }
}

// -------- k_mma: mma.sync split-bf16 GEMM, CTA tile 128x128, fused epilogue ----
// smem tiles: row stride 136 bf16 = 272B (17x16B -> conflict-free ldmatrix)
#define TSTRIDE 272
#define TILE_B  (128 * TSTRIDE)        // 34816 B per tile
#define OFF_AH  0
#define OFF_AL  TILE_B
#define OFF_BH  (2 * TILE_B)
#define OFF_BL  (3 * TILE_B)
#define SMEM_MMA (4 * TILE_B)          // 139264 B

__global__ __launch_bounds__(256) void k_mma(){
  extern __shared__ char smem[];
  __shared__ float aS[128];
  __shared__ float sq2S[128];
  __shared__ unsigned int smax[128];
  __shared__ float sred[8];

  int tid = threadIdx.x;
  int wid = tid >> 5, lid = tid & 31;
  int rowBase = blockIdx.y * 128;
  int colBase = blockIdx.x * 128;
  int warpM = (wid >> 2) * 64;
  int warpN = (wid & 3) * 32;

  if (tid < 128){
    aS[tid]   = d_a[rowBase + tid];
    sq2S[tid] = d_sq2[colBase + tid];
    smax[tid] = 0u;
  }

  // global -> smem: 128 rows x 16 chunks of 16B per tile
  #pragma unroll
  for (int p = 0; p < 8; p++){
    int q  = tid + p * 256;
    int r  = q >> 4;
    int c8 = q & 15;
    uint32_t so = (uint32_t)(r * TSTRIDE + c8 * 16);
    *(uint4*)(smem + OFF_AH + so) = *((const uint4*)(d_p1h + (rowBase + r) * DD) + c8);
    *(uint4*)(smem + OFF_AL + so) = *((const uint4*)(d_p1l + (rowBase + r) * DD) + c8);
    *(uint4*)(smem + OFF_BH + so) = *((const uint4*)(d_p2h + (colBase + r) * DD) + c8);
    *(uint4*)(smem + OFF_BL + so) = *((const uint4*)(d_p2l + (colBase + r) * DD) + c8);
  }
  __syncthreads();

  uint32_t sb   = smem_u32(smem);
  uint32_t sbAH = sb + OFF_AH, sbAL = sb + OFF_AL;
  uint32_t sbBH = sb + OFF_BH, sbBL = sb + OFF_BL;

  float acc[4][4][4];
  #pragma unroll
  for (int i = 0; i < 4; i++)
    #pragma unroll
    for (int j = 0; j < 4; j++)
      #pragma unroll
      for (int c = 0; c < 4; c++) acc[i][j][c] = 0.0f;

  #pragma unroll
  for (int ks = 0; ks < 8; ks++){
    uint32_t ah[4][4], al[4][4];
    #pragma unroll
    for (int mt = 0; mt < 4; mt++){
      int row = warpM + mt * 16 + (lid & 7) + ((lid >> 3) & 1) * 8;
      int col = ks * 16 + ((lid >> 4) & 1) * 8;
      uint32_t off = (uint32_t)(row * TSTRIDE + col * 2);
      ldmx4(ah[mt], sbAH + off);
      ldmx4(al[mt], sbAL + off);
    }
    uint32_t bh[2][4], bl[2][4];
    #pragma unroll
    for (int np = 0; np < 2; np++){
      int row = warpN + np * 16 + (lid & 7) + ((lid >> 4) & 1) * 8;
      int col = ks * 16 + ((lid >> 3) & 1) * 8;
      uint32_t off = (uint32_t)(row * TSTRIDE + col * 2);
      ldmx4(bh[np], sbBH + off);
      ldmx4(bl[np], sbBL + off);
    }
    #pragma unroll
    for (int mt = 0; mt < 4; mt++)
      #pragma unroll
      for (int nt = 0; nt < 4; nt++){
        const uint32_t* bhf = &bh[nt >> 1][(nt & 1) * 2];
        const uint32_t* blf = &bl[nt >> 1][(nt & 1) * 2];
        mma_bf16(acc[mt][nt], ah[mt], bhf);   // Ah*Bh
        mma_bf16(acc[mt][nt], ah[mt], blf);   // Ah*Bl
        mma_bf16(acc[mt][nt], al[mt], bhf);   // Al*Bh
      }
  }

  // ---- epilogue: loss = relu(2c + a_i - sq2_j), skip diagonal ----
  int g = lid >> 2;          // row group within 8x8 frag
  int tg = lid & 3;          // col pair selector
  float lsum = 0.0f;
  float rm[8];
  #pragma unroll
  for (int i = 0; i < 8; i++) rm[i] = 0.0f;

  #pragma unroll
  for (int mt = 0; mt < 4; mt++)
    #pragma unroll
    for (int nt = 0; nt < 4; nt++)
      #pragma unroll
      for (int c = 0; c < 4; c++){
        int sub = c >> 1;                       // 0: rows g, 1: rows g+8
        int m_l = warpM + mt * 16 + g + sub * 8;
        int n_l = warpN + nt * 8 + 2 * tg + (c & 1);
        float loss = fmaxf(fmaf(2.0f, acc[mt][nt][c], aS[m_l] - sq2S[n_l]), 0.0f);
        if (rowBase + m_l != colBase + n_l){
          lsum += loss;
          rm[mt * 2 + sub] = fmaxf(rm[mt * 2 + sub], loss);
        }
      }

  // row-max reduce across the 4 lanes sharing g (lanes 4g..4g+3)
  #pragma unroll
  for (int i = 0; i < 8; i++){
    rm[i] = fmaxf(rm[i], __shfl_xor_sync(0xffffffffu, rm[i], 1));
    rm[i] = fmaxf(rm[i], __shfl_xor_sync(0xffffffffu, rm[i], 2));
  }
  if (tg == 0){
    #pragma unroll
    for (int i = 0; i < 8; i++){
      int m_l = warpM + (i >> 1) * 16 + g + (i & 1) * 8;
      atomicMax(&smax[m_l], __float_as_uint(rm[i]));
    }
  }
  lsum = warpRedSumF(lsum);
  if (lid == 0) sred[wid] = lsum;
  __syncthreads();

  if (tid < 128) atomicMax(&d_M[rowBase + tid], smax[tid]);
  if (tid == 0){
    double bs = 0.0;
    #pragma unroll
    for (int w = 0; w < 8; w++) bs += (double)sred[w];
    atomicAdd(&d_sum, bs);
  }
}

// -------- k_select --------
__global__ __launch_bounds__(1024) void k_select(){
  __shared__ float sM[NN];
  __shared__ int   shi[32];
  __shared__ float shf[32];
  __shared__ int   cnt_s;
  int tid = threadIdx.x;
  float lm = 0.0f;
  for (int i = tid; i < NN; i += 1024){
    float v = __uint_as_float(d_M[i]);
    sM[i] = v;
    lm = fmaxf(lm, v);
  }
  __syncthreads();
  float gmax = blockRedMaxF(lm, shf);

  float lo = 0.0f, hi = gmax * 1.0001f + 1e-6f;
  for (int it = 0; it < 32; it++){
    float mid = 0.5f * (lo + hi);
    int c = 0;
    for (int i = tid; i < NN; i += 1024) c += (sM[i] >= mid) ? 1 : 0;
    c = blockRedSumI(c, shi);
    if (c >= TOPK) lo = mid; else hi = mid;
  }
  float tau = lo * 0.9999f - 0.01f;   // covers bf16-split + fp32-recompute noise

  if (tid == 0) cnt_s = 0;
  __syncthreads();
  for (int i = tid; i < NN; i += 1024){
    if (sM[i] >= tau){
      int p = atomicAdd(&cnt_s, 1);
      if (p < SELCAP) d_selRows[p] = i;
    }
  }
  __syncthreads();
  if (tid == 0){
    d_nsel = (cnt_s < SELCAP) ? cnt_s : SELCAP;
    d_tau  = tau;
    d_gmax = gmax;
  }
}

// -------- k_collect: exact fp32 recompute of selected rows --------
__global__ __launch_bounds__(256) void k_collect(const float* __restrict__ p1,
                                                 const float* __restrict__ p2){
  int nsel = d_nsel;
  int rt = blockIdx.y;
  if (rt * 64 >= nsel) return;
  int nrows = min(64, nsel - rt * 64);

  __shared__ __align__(16) float As[64][DD];
  __shared__ float aSS[64];
  __shared__ int   ri[64];
  int tid = threadIdx.x;
  if (tid < 64){
    if (tid < nrows){
      int r = d_selRows[rt * 64 + tid];
      ri[tid] = r;
      aSS[tid] = d_a[r];
    } else { ri[tid] = -1; aSS[tid] = 0.0f; }
  }
  __syncthreads();
  #pragma unroll
  for (int p = 0; p < 8; p++){
    int q  = tid + p * 256;
    int r  = q >> 5;
    int c4 = q & 31;
    float4 v = make_float4(0.f, 0.f, 0.f, 0.f);
    if (r < nrows) v = *(const float4*)(p1 + ri[r] * DD + c4 * 4);
    *(float4*)&As[r][c4 * 4] = v;
  }
  __syncthreads();

  int col = blockIdx.x * 256 + tid;
  float acc[64];
  #pragma unroll
  for (int r = 0; r < 64; r++) acc[r] = 0.0f;
  const float4* p2r = (const float4*)(p2 + col * DD);
  for (int k4 = 0; k4 < 32; k4++){
    float4 b = p2r[k4];
    #pragma unroll
    for (int r = 0; r < 64; r++){
      float4 a = *(const float4*)&As[r][k4 * 4];
      acc[r] = fmaf(a.x, b.x, acc[r]);
      acc[r] = fmaf(a.y, b.y, acc[r]);
      acc[r] = fmaf(a.z, b.z, acc[r]);
      acc[r] = fmaf(a.w, b.w, acc[r]);
    }
  }
  float s2c = d_sq2[col];
  float tau = d_tau;
  #pragma unroll
  for (int r = 0; r < 64; r++){
    if (r < nrows){
      float loss = fmaxf(fmaf(2.0f, acc[r], aSS[r] - s2c), 0.0f);
      if (loss >= tau && ri[r] != col){
        int p = atomicAdd(&d_ncand, 1);
        if (p < CANDCAP) d_cand[p] = loss;
      }
    }
  }
}

// -------- k_final: exact top-512 stats --------
__global__ __launch_bounds__(1024) void k_final(float* __restrict__ out){
  __shared__ float shf[32];
  __shared__ int   shi[32];
  int tid = threadIdx.x;
  int nc = d_ncand;
  if (nc > CANDCAP) nc = CANDCAP;
  float gmax = d_gmax;

  int pc = 0; float ps = 0.0f;
  for (int i = tid; i < nc; i += 1024){
    float v = d_cand[i];
    if (v > 0.0f){ pc++; ps += v; }
  }
  int pcnt   = blockRedSumI(pc, shi);
  float psum = blockRedSumF(ps, shf);

  float avg;
  if (pcnt >= TOPK){
    float lo = 0.0f, hi = gmax * 1.0001f + 1e-6f;
    for (int it = 0; it < 40; it++){
      float mid = 0.5f * (lo + hi);
      int c = 0;
      for (int i = tid; i < nc; i += 1024) c += (d_cand[i] >= mid) ? 1 : 0;
      c = blockRedSumI(c, shi);
      if (c >= TOPK) lo = mid; else hi = mid;
    }
    int ch = 0; float sh = 0.0f;
    for (int i = tid; i < nc; i += 1024){
      float v = d_cand[i];
      if (v >= hi){ ch++; sh += v; }
    }
    int   chi = blockRedSumI(ch, shi);
    float shs = blockRedSumF(sh, shf);
    avg = (shs + (float)(TOPK - chi) * lo) / (float)TOPK;
  } else if (pcnt > 0){
    avg = psum / (float)pcnt;
  } else {
    avg = gmax;
  }

  if (tid == 0){
    out[0] = avg;
    out[1] = (float)(d_sum / ((double)NN * (double)(NN - 1)));
  }
}

extern "C" void kernel_launch(void* const* d_in, const int* in_sizes, int n_in,
                              void* d_out, int out_size){
  (void)in_sizes; (void)n_in; (void)out_size;
  const float* p1 = (const float*)d_in[0];
  const float* p2 = (const float*)d_in[1];
  float* out = (float*)d_out;

  static int attrDone = 0;
  if (!attrDone){
    cudaFuncSetAttribute(k_mma, cudaFuncAttributeMaxDynamicSharedMemorySize, SMEM_MMA);
    attrDone = 1;
  }

  k_init   <<<(NN + 255) / 256, 256>>>();
  k_conv   <<<1024, 256>>>(p1, p2);
  k_prep   <<<NN / 8, 256>>>(p1, p2);
  k_mma    <<<dim3(64, 64), 256, SMEM_MMA>>>();
  k_select <<<1, 1024>>>();
  k_collect<<<dim3(32, 64), 256>>>(p1, p2);
  k_final  <<<1, 1024>>>(out);
}

// round 17
// speedup vs baseline: 1.7165x; 1.0265x over previous
#include <cuda_runtime.h>
#include <cuda_bf16.h>
#include <cstdint>

#define NN 8192
#define DD 128
#define MARGIN 0.3f
#define TOPK 512
#define SELCAP 4096
#define CANDCAP 65536

// ---------------- device scratch ----------------
__device__ float        d_a[NN];
__device__ float        d_sq2[NN];
__device__ unsigned int d_M[NN];
__device__ double       d_sum;
__device__ float        d_tau;
__device__ float        d_gmax;
__device__ int          d_nsel;
__device__ int          d_selRows[SELCAP];
__device__ int          d_ncand;
__device__ float        d_cand[CANDCAP];
// bf16 hi/lo split copies of inputs
__device__ __nv_bfloat16 d_p1h[NN*DD];
__device__ __nv_bfloat16 d_p1l[NN*DD];
__device__ __nv_bfloat16 d_p2h[NN*DD];
__device__ __nv_bfloat16 d_p2l[NN*DD];

// ---------------- SIMT tensor helpers ----------------
__device__ __forceinline__ uint32_t smem_u32(const void* p){
  uint32_t a;
  asm("{ .reg .u64 t; cvta.to.shared.u64 t, %1; cvt.u32.u64 %0, t; }" : "=r"(a) : "l"(p));
  return a;
}
__device__ __forceinline__ void ldmx4(uint32_t* r, uint32_t addr){
  asm volatile("ldmatrix.sync.aligned.m8n8.x4.shared.b16 {%0,%1,%2,%3}, [%4];"
    : "=r"(r[0]), "=r"(r[1]), "=r"(r[2]), "=r"(r[3]) : "r"(addr));
}
__device__ __forceinline__ void mma_bf16(float* d, const uint32_t* a, const uint32_t* b){
  asm volatile(
    "mma.sync.aligned.m16n8k16.row.col.f32.bf16.bf16.f32 "
    "{%0,%1,%2,%3}, {%4,%5,%6,%7}, {%8,%9}, {%0,%1,%2,%3};"
    : "+f"(d[0]), "+f"(d[1]), "+f"(d[2]), "+f"(d[3])
    : "r"(a[0]), "r"(a[1]), "r"(a[2]), "r"(a[3]), "r"(b[0]), "r"(b[1]));
}

// ---------------- reductions ----------------
__device__ __forceinline__ float warpRedSumF(float v){
  #pragma unroll
  for (int o=16;o;o>>=1) v += __shfl_xor_sync(0xffffffffu, v, o);
  return v;
}
__device__ __forceinline__ int warpRedSumI(int v){
  #pragma unroll
  for (int o=16;o;o>>=1) v += __shfl_xor_sync(0xffffffffu, v, o);
  return v;
}
__device__ __forceinline__ float warpRedMaxF(float v){
  #pragma unroll
  for (int o=16;o;o>>=1) v = fmaxf(v, __shfl_xor_sync(0xffffffffu, v, o));
  return v;
}
__device__ __forceinline__ int blockRedSumI(int v, int* sh){
  v = warpRedSumI(v);
  int w = threadIdx.x >> 5, l = threadIdx.x & 31;
  if (l == 0) sh[w] = v;
  __syncthreads();
  if (w == 0){ int x = sh[l]; x = warpRedSumI(x); if (l == 0) sh[0] = x; }
  __syncthreads();
  int r = sh[0];
  __syncthreads();
  return r;
}
__device__ __forceinline__ float blockRedSumF(float v, float* sh){
  v = warpRedSumF(v);
  int w = threadIdx.x >> 5, l = threadIdx.x & 31;
  if (l == 0) sh[w] = v;
  __syncthreads();
  if (w == 0){ float x = sh[l]; x = warpRedSumF(x); if (l == 0) sh[0] = x; }
  __syncthreads();
  float r = sh[0];
  __syncthreads();
  return r;
}
__device__ __forceinline__ float blockRedMaxF(float v, float* sh){
  v = warpRedMaxF(v);
  int w = threadIdx.x >> 5, l = threadIdx.x & 31;
  if (l == 0) sh[w] = v;
  __syncthreads();
  if (w == 0){ float x = sh[l]; x = warpRedMaxF(x); if (l == 0) sh[0] = x; }
  __syncthreads();
  float r = sh[0];
  __syncthreads();
  return r;
}

// -------- k0: reset scratch --------
__global__ void k_init(){
  int i = blockIdx.x * blockDim.x + threadIdx.x;
  if (i < NN) d_M[i] = 0u;
  if (i == 0){ d_sum = 0.0; d_ncand = 0; d_nsel = 0; }
}

// -------- k_conv: fp32 -> bf16 hi/lo split --------
__global__ void k_conv(const float* __restrict__ p1, const float* __restrict__ p2){
  int base = blockIdx.x * blockDim.x + threadIdx.x;
  int stride = gridDim.x * blockDim.x;
  for (int i = base; i < NN*DD; i += stride){
    float x = p1[i];
    __nv_bfloat16 h = __float2bfloat16(x);
    d_p1h[i] = h;
    d_p1l[i] = __float2bfloat16(x - __bfloat162float(h));
    float y = p2[i];
    __nv_bfloat16 g = __float2bfloat16(y);
    d_p2h[i] = g;
    d_p2l[i] = __float2bfloat16(y - __bfloat162float(g));
  }
}

// -------- k_prep: exact fp32 sq2 / a --------
__global__ void k_prep(const float* __restrict__ p1, const float* __restrict__ p2){
  int warp = (blockIdx.x * blockDim.x + threadIdx.x) >> 5;
  int lane = threadIdx.x & 31;
  if (warp >= NN) return;
  const float4* p1r = (const float4*)(p1 + warp * DD);
  const float4* p2r = (const float4*)(p2 + warp * DD);
  float4 x = p1r[lane];
  float4 y = p2r[lane];
  float sq = y.x*y.x + y.y*y.y + y.z*y.z + y.w*y.w;
  float ci = x.x*y.x + x.y*y.y + x.z*y.z + x.w*y.w;
  sq = warpRedSumF(sq);
  ci = warpRedSumF(ci);
  if (lane == 0){
    d_sq2[warp] = sq;
    d_a[warp]   = sq - 2.0f * ci + MARGIN;
  }
}

// -------- k_mma: split-bf16 GEMM, CTA tile 128x64, 2 CTAs/SM, fused epilogue ----
// smem row stride 272B (17x16B, conflict-free ldmatrix)
#define TSTRIDE 272
#define ATILE_B (128 * TSTRIDE)        // 34816 B
#define BTILE_B (64  * TSTRIDE)        // 17408 B
#define OFF_AH  0
#define OFF_AL  ATILE_B
#define OFF_BH  (2 * ATILE_B)
#define OFF_BL  (2 * ATILE_B + BTILE_B)
#define SMEM_MMA (2 * ATILE_B + 2 * BTILE_B)   // 104448 B -> 2 CTAs/SM

__global__ __launch_bounds__(256, 2) void k_mma(){
  extern __shared__ char smem[];
  __shared__ float aS[128];
  __shared__ float sq2S[64];
  __shared__ unsigned int smax[128];
  __shared__ float sred[8];

  int tid = threadIdx.x;
  int wid = tid >> 5, lid = tid & 31;
  int rowBase = blockIdx.y * 128;
  int colBase = blockIdx.x * 64;
  int warpM = (wid & 3) * 32;          // 4 M-slices of 32
  int warpN = (wid >> 2) * 32;         // 2 N-slices of 32

  if (tid < 128){
    aS[tid]   = d_a[rowBase + tid];
    smax[tid] = 0u;
  }
  if (tid < 64) sq2S[tid] = d_sq2[colBase + tid];

  // A tiles: 128 rows x 16 c8 chunks -> 2048 uint4 per tile
  #pragma unroll
  for (int p = 0; p < 8; p++){
    int q  = tid + p * 256;
    int r  = q >> 4;
    int c8 = q & 15;
    uint32_t so = (uint32_t)(r * TSTRIDE + c8 * 16);
    *(uint4*)(smem + OFF_AH + so) = *((const uint4*)(d_p1h + (rowBase + r) * DD) + c8);
    *(uint4*)(smem + OFF_AL + so) = *((const uint4*)(d_p1l + (rowBase + r) * DD) + c8);
  }
  // B tiles: 64 rows x 16 c8 chunks -> 1024 uint4 per tile
  #pragma unroll
  for (int p = 0; p < 4; p++){
    int q  = tid + p * 256;
    int r  = q >> 4;
    int c8 = q & 15;
    uint32_t so = (uint32_t)(r * TSTRIDE + c8 * 16);
    *(uint4*)(smem + OFF_BH + so) = *((const uint4*)(d_p2h + (colBase + r) * DD) + c8);
    *(uint4*)(smem + OFF_BL + so) = *((const uint4*)(d_p2l + (colBase + r) * DD) + c8);
  }
  __syncthreads();

  uint32_t sb   = smem_u32(smem);
  uint32_t sbAH = sb + OFF_AH, sbAL = sb + OFF_AL;
  uint32_t sbBH = sb + OFF_BH, sbBL = sb + OFF_BL;

  float acc[2][4][4];
  #pragma unroll
  for (int i = 0; i < 2; i++)
    #pragma unroll
    for (int j = 0; j < 4; j++)
      #pragma unroll
      for (int c = 0; c < 4; c++) acc[i][j][c] = 0.0f;

  #pragma unroll
  for (int ks = 0; ks < 8; ks++){
    uint32_t ah[2][4], al[2][4];
    #pragma unroll
    for (int mt = 0; mt < 2; mt++){
      int row = warpM + mt * 16 + (lid & 7) + ((lid >> 3) & 1) * 8;
      int col = ks * 16 + ((lid >> 4) & 1) * 8;
      uint32_t off = (uint32_t)(row * TSTRIDE + col * 2);
      ldmx4(ah[mt], sbAH + off);
      ldmx4(al[mt], sbAL + off);
    }
    uint32_t bh[2][4], bl[2][4];
    #pragma unroll
    for (int np = 0; np < 2; np++){
      int row = warpN + np * 16 + (lid & 7) + ((lid >> 4) & 1) * 8;
      int col = ks * 16 + ((lid >> 3) & 1) * 8;
      uint32_t off = (uint32_t)(row * TSTRIDE + col * 2);
      ldmx4(bh[np], sbBH + off);
      ldmx4(bl[np], sbBL + off);
    }
    #pragma unroll
    for (int mt = 0; mt < 2; mt++)
      #pragma unroll
      for (int nt = 0; nt < 4; nt++){
        const uint32_t* bhf = &bh[nt >> 1][(nt & 1) * 2];
        const uint32_t* blf = &bl[nt >> 1][(nt & 1) * 2];
        mma_bf16(acc[mt][nt], ah[mt], bhf);   // Ah*Bh
        mma_bf16(acc[mt][nt], ah[mt], blf);   // Ah*Bl
        mma_bf16(acc[mt][nt], al[mt], bhf);   // Al*Bh
      }
  }

  // ---- epilogue: loss = relu(2c + a_i - sq2_j), skip diagonal ----
  int g = lid >> 2;
  int tg = lid & 3;
  float lsum = 0.0f;
  float rm[4];
  #pragma unroll
  for (int i = 0; i < 4; i++) rm[i] = 0.0f;

  #pragma unroll
  for (int mt = 0; mt < 2; mt++)
    #pragma unroll
    for (int nt = 0; nt < 4; nt++)
      #pragma unroll
      for (int c = 0; c < 4; c++){
        int sub = c >> 1;
        int m_l = warpM + mt * 16 + g + sub * 8;
        int n_l = warpN + nt * 8 + 2 * tg + (c & 1);
        float loss = fmaxf(fmaf(2.0f, acc[mt][nt][c], aS[m_l] - sq2S[n_l]), 0.0f);
        if (rowBase + m_l != colBase + n_l){
          lsum += loss;
          rm[mt * 2 + sub] = fmaxf(rm[mt * 2 + sub], loss);
        }
      }

  #pragma unroll
  for (int i = 0; i < 4; i++){
    rm[i] = fmaxf(rm[i], __shfl_xor_sync(0xffffffffu, rm[i], 1));
    rm[i] = fmaxf(rm[i], __shfl_xor_sync(0xffffffffu, rm[i], 2));
  }
  if (tg == 0){
    #pragma unroll
    for (int i = 0; i < 4; i++){
      int m_l = warpM + (i >> 1) * 16 + g + (i & 1) * 8;
      atomicMax(&smax[m_l], __float_as_uint(rm[i]));
    }
  }
  lsum = warpRedSumF(lsum);
  if (lid == 0) sred[wid] = lsum;
  __syncthreads();

  if (tid < 128) atomicMax(&d_M[rowBase + tid], smax[tid]);
  if (tid == 0){
    double bs = 0.0;
    #pragma unroll
    for (int w = 0; w < 8; w++) bs += (double)sred[w];
    atomicAdd(&d_sum, bs);
  }
}

// -------- k_select --------
__global__ __launch_bounds__(1024) void k_select(){
  __shared__ float sM[NN];
  __shared__ int   shi[32];
  __shared__ float shf[32];
  __shared__ int   cnt_s;
  int tid = threadIdx.x;
  float lm = 0.0f;
  for (int i = tid; i < NN; i += 1024){
    float v = __uint_as_float(d_M[i]);
    sM[i] = v;
    lm = fmaxf(lm, v);
  }
  __syncthreads();
  float gmax = blockRedMaxF(lm, shf);

  float lo = 0.0f, hi = gmax * 1.0001f + 1e-6f;
  for (int it = 0; it < 20; it++){
    float mid = 0.5f * (lo + hi);
    int c = 0;
    for (int i = tid; i < NN; i += 1024) c += (sM[i] >= mid) ? 1 : 0;
    c = blockRedSumI(c, shi);
    if (c >= TOPK) lo = mid; else hi = mid;
  }
  float tau = lo * 0.999f - 0.01f;   // covers bf16-split + fp32-recompute + search slack

  if (tid == 0) cnt_s = 0;
  __syncthreads();
  for (int i = tid; i < NN; i += 1024){
    if (sM[i] >= tau){
      int p = atomicAdd(&cnt_s, 1);
      if (p < SELCAP) d_selRows[p] = i;
    }
  }
  __syncthreads();
  if (tid == 0){
    d_nsel = (cnt_s < SELCAP) ? cnt_s : SELCAP;
    d_tau  = tau;
    d_gmax = gmax;
  }
}

// -------- k_collect: exact fp32 recompute of selected rows --------
__global__ __launch_bounds__(256) void k_collect(const float* __restrict__ p1,
                                                 const float* __restrict__ p2){
  int nsel = d_nsel;
  int rt = blockIdx.y;
  if (rt * 64 >= nsel) return;
  int nrows = min(64, nsel - rt * 64);

  __shared__ __align__(16) float As[64][DD];
  __shared__ float aSS[64];
  __shared__ int   ri[64];
  int tid = threadIdx.x;
  if (tid < 64){
    if (tid < nrows){
      int r = d_selRows[rt * 64 + tid];
      ri[tid] = r;
      aSS[tid] = d_a[r];
    } else { ri[tid] = -1; aSS[tid] = 0.0f; }
  }
  __syncthreads();
  #pragma unroll
  for (int p = 0; p < 8; p++){
    int q  = tid + p * 256;
    int r  = q >> 5;
    int c4 = q & 31;
    float4 v = make_float4(0.f, 0.f, 0.f, 0.f);
    if (r < nrows) v = *(const float4*)(p1 + ri[r] * DD + c4 * 4);
    *(float4*)&As[r][c4 * 4] = v;
  }
  __syncthreads();

  int col = blockIdx.x * 256 + tid;
  float acc[64];
  #pragma unroll
  for (int r = 0; r < 64; r++) acc[r] = 0.0f;
  const float4* p2r = (const float4*)(p2 + col * DD);
  for (int k4 = 0; k4 < 32; k4++){
    float4 b = p2r[k4];
    #pragma unroll
    for (int r = 0; r < 64; r++){
      float4 a = *(const float4*)&As[r][k4 * 4];
      acc[r] = fmaf(a.x, b.x, acc[r]);
      acc[r] = fmaf(a.y, b.y, acc[r]);
      acc[r] = fmaf(a.z, b.z, acc[r]);
      acc[r] = fmaf(a.w, b.w, acc[r]);
    }
  }
  float s2c = d_sq2[col];
  float tau = d_tau;
  #pragma unroll
  for (int r = 0; r < 64; r++){
    if (r < nrows){
      float loss = fmaxf(fmaf(2.0f, acc[r], aSS[r] - s2c), 0.0f);
      if (loss >= tau && ri[r] != col){
        int p = atomicAdd(&d_ncand, 1);
        if (p < CANDCAP) d_cand[p] = loss;
      }
    }
  }
}

// -------- k_final: exact top-512 stats --------
__global__ __launch_bounds__(1024) void k_final(float* __restrict__ out){
  __shared__ float shf[32];
  __shared__ int   shi[32];
  int tid = threadIdx.x;
  int nc = d_ncand;
  if (nc > CANDCAP) nc = CANDCAP;
  float gmax = d_gmax;

  int pc = 0; float ps = 0.0f;
  for (int i = tid; i < nc; i += 1024){
    float v = d_cand[i];
    if (v > 0.0f){ pc++; ps += v; }
  }
  int pcnt   = blockRedSumI(pc, shi);
  float psum = blockRedSumF(ps, shf);

  float avg;
  if (pcnt >= TOPK){
    float lo = 0.0f, hi = gmax * 1.0001f + 1e-6f;
    for (int it = 0; it < 30; it++){
      float mid = 0.5f * (lo + hi);
      int c = 0;
      for (int i = tid; i < nc; i += 1024) c += (d_cand[i] >= mid) ? 1 : 0;
      c = blockRedSumI(c, shi);
      if (c >= TOPK) lo = mid; else hi = mid;
    }
    int ch = 0; float sh = 0.0f;
    for (int i = tid; i < nc; i += 1024){
      float v = d_cand[i];
      if (v >= hi){ ch++; sh += v; }
    }
    int   chi = blockRedSumI(ch, shi);
    float shs = blockRedSumF(sh, shf);
    avg = (shs + (float)(TOPK - chi) * lo) / (float)TOPK;
  } else if (pcnt > 0){
    avg = psum / (float)pcnt;
  } else {
    avg = gmax;
  }

  if (tid == 0){
    out[0] = avg;
    out[1] = (float)(d_sum / ((double)NN * (double)(NN - 1)));
  }
}

extern "C" void kernel_launch(void* const* d_in, const int* in_sizes, int n_in,
                              void* d_out, int out_size){
  (void)in_sizes; (void)n_in; (void)out_size;
  const float* p1 = (const float*)d_in[0];
  const float* p2 = (const float*)d_in[1];
  float* out = (float*)d_out;

  static int attrDone = 0;
  if (!attrDone){
    cudaFuncSetAttribute(k_mma, cudaFuncAttributeMaxDynamicSharedMemorySize, SMEM_MMA);
    attrDone = 1;
  }

  k_init   <<<(NN + 255) / 256, 256>>>();
  k_conv   <<<1024, 256>>>(p1, p2);
  k_prep   <<<NN / 8, 256>>>(p1, p2);
  k_mma    <<<dim3(NN / 64, NN / 128), 256, SMEM_MMA>>>();
  k_select <<<1, 1024>>>();
  k_collect<<<dim3(32, 64), 256>>>(p1, p2);
  k_final  <<<1, 1024>>>(out);
}